// round 1
// baseline (speedup 1.0000x reference)
#include <cuda_runtime.h>
#include <math.h>

#define BB 8
#define SS 4096
#define HH 768
#define MS 64
#define F1 4096
#define F2 256
#define SEPTOK 2
#define NSPLIT 16
#define MROWS (BB*MS)   // 512

// ---------------- scratch (device globals; no allocation allowed) ----------
__device__ float g_sent[MROWS*HH];            // 1.5 MB
__device__ float g_x1[MROWS*F1];              // 8 MB
__device__ float g_x2p[NSPLIT*MROWS*F2];      // 8 MB
__device__ float g_x2[MROWS*F2];              // 0.5 MB
__device__ int   g_sep_pos[BB][SS];
__device__ int   g_nsep[BB];

__device__ __forceinline__ float gelu_exact(float x) {
    return 0.5f * x * (1.0f + erff(x * 0.70710678118654752f));
}

// ---------------- 1) sep scan: positions of SEP tokens per row -------------
// ids may be int32 or int64 (jax x64 ambiguity). Detect: values are >=2, so
// if interpreted as int32, element[1]==0 only when buffer is int64
// (little-endian high word of a small positive value).
__global__ void sep_scan_kernel(const int* __restrict__ ids32) {
    const int b = blockIdx.x;
    const int tid = threadIdx.x;                 // 256 threads
    const int stride = (ids32[1] == 0) ? 2 : 1;  // int64 -> read low words
    const int* row = ids32 + (size_t)b * SS * stride;

    __shared__ int cnt[256];
    __shared__ int excl[257];

    const int base = tid * 16;                   // 16 tokens per thread
    int c = 0;
    #pragma unroll
    for (int i = 0; i < 16; i++)
        if (row[(base + i) * stride] == SEPTOK) c++;
    cnt[tid] = c;
    __syncthreads();

    if (tid == 0) {
        int acc = 0;
        for (int i = 0; i < 256; i++) { excl[i] = acc; acc += cnt[i]; }
        excl[256] = acc;
        g_nsep[b] = acc;
    }
    __syncthreads();

    int off = excl[tid];
    for (int i = 0; i < 16; i++) {
        if (row[(base + i) * stride] == SEPTOK)
            g_sep_pos[b][off++] = base + i;
    }
}

// ---------------- 2) per-sentence mean pooling -----------------------------
// Reference semantics:
//   seg(t) = #seps strictly before t; first sep included in segment 0,
//   later seps excluded; trailing segment (seg==n_sep, n_sep>0) excludes
//   token S-1; segments with index >= MS dumped; empty segments -> zeros.
__global__ void pool_kernel(const float* __restrict__ hidden) {
    const int s   = blockIdx.x;   // 0..63
    const int b   = blockIdx.y;   // 0..7
    const int tid = threadIdx.x;  // 256 (HH = 3*256)
    const int n   = g_nsep[b];

    int t0 = 0, t1 = 0;
    if (n == 0) {
        if (s == 0) { t0 = 0; t1 = SS; }
    } else if (s < n) {           // s < MS always (grid)
        if (s == 0) { t0 = 0; t1 = g_sep_pos[b][0] + 1; }   // includes first sep
        else        { t0 = g_sep_pos[b][s-1] + 1; t1 = g_sep_pos[b][s]; }
    } else if (s == n) {          // trailing segment (only reachable if n < MS)
        t0 = g_sep_pos[b][n-1] + 1; t1 = SS - 1;            // excludes last token
    }

    float a0 = 0.f, a1 = 0.f, a2 = 0.f;
    const float* hb = hidden + (size_t)b * SS * HH;
    #pragma unroll 4
    for (int t = t0; t < t1; t++) {
        const float* p = hb + (size_t)t * HH + tid;
        a0 += p[0];
        a1 += p[256];
        a2 += p[512];
    }
    const int cnt = t1 - t0;
    const float inv = (cnt > 0) ? (1.0f / (float)cnt) : 0.0f;
    float* o = g_sent + (size_t)(b * MS + s) * HH + tid;
    o[0]   = a0 * inv;
    o[256] = a1 * inv;
    o[512] = a2 * inv;
}

// ---------------- 3) fp32 SGEMM, 128x128x8 tile, 8x8 microtile -------------
// EPI==1: C = gelu(A@B + bias)       (write to C)
// EPI==0: split-K partial: C[z] = A@B over K-chunk z (no bias/activation)
template<int EPI>
__global__ __launch_bounds__(256)
void sgemm_k(const float* __restrict__ A, const float* __restrict__ Bm,
             const float* __restrict__ bias, float* __restrict__ C,
             int M, int N, int K, int kLen)
{
    __shared__ float As[8][128];
    __shared__ float Bs[8][128];

    const int tid = threadIdx.x;
    const int m0 = blockIdx.y * 128;
    const int n0 = blockIdx.x * 128;
    const int kStart = blockIdx.z * kLen;
    float* Cp = (EPI == 0) ? (C + (size_t)blockIdx.z * M * N) : C;

    const int aRow = tid >> 1,  aCol = (tid & 1) * 4;   // A tile: 128 rows x 8 k
    const int bRow = tid >> 5,  bCol = (tid & 31) * 4;  // B tile: 8 k x 128 cols
    const float* Ag = A  + (size_t)(m0 + aRow) * K + kStart + aCol;
    const float* Bg = Bm + (size_t)(kStart + bRow) * N + n0 + bCol;

    const int ty = tid >> 4, tx = tid & 15;

    float acc[8][8];
    #pragma unroll
    for (int i = 0; i < 8; i++)
        #pragma unroll
        for (int j = 0; j < 8; j++) acc[i][j] = 0.f;

    for (int k = 0; k < kLen; k += 8) {
        float4 av = *(const float4*)(Ag + k);
        float4 bv = *(const float4*)(Bg + (size_t)k * N);
        As[aCol + 0][aRow] = av.x;
        As[aCol + 1][aRow] = av.y;
        As[aCol + 2][aRow] = av.z;
        As[aCol + 3][aRow] = av.w;
        *(float4*)&Bs[bRow][bCol] = bv;
        __syncthreads();

        #pragma unroll
        for (int kk = 0; kk < 8; kk++) {
            float4 a0 = *(const float4*)&As[kk][ty * 8];
            float4 a1 = *(const float4*)&As[kk][ty * 8 + 4];
            float4 b0 = *(const float4*)&Bs[kk][tx * 8];
            float4 b1 = *(const float4*)&Bs[kk][tx * 8 + 4];
            float ar[8] = {a0.x, a0.y, a0.z, a0.w, a1.x, a1.y, a1.z, a1.w};
            float br[8] = {b0.x, b0.y, b0.z, b0.w, b1.x, b1.y, b1.z, b1.w};
            #pragma unroll
            for (int i = 0; i < 8; i++)
                #pragma unroll
                for (int j = 0; j < 8; j++)
                    acc[i][j] = fmaf(ar[i], br[j], acc[i][j]);
        }
        __syncthreads();
    }

    #pragma unroll
    for (int i = 0; i < 8; i++) {
        const int m = m0 + ty * 8 + i;
        #pragma unroll
        for (int j = 0; j < 8; j++) {
            const int n = n0 + tx * 8 + j;
            float v = acc[i][j];
            if (EPI == 1) v = gelu_exact(v + bias[n]);
            Cp[(size_t)m * N + n] = v;
        }
    }
}

// ---------------- 4) split-K reduce + bias + GELU --------------------------
__global__ void reduce_gelu_kernel(const float* __restrict__ b2) {
    const int idx = blockIdx.x * blockDim.x + threadIdx.x;  // MROWS*F2
    float s = 0.f;
    #pragma unroll
    for (int i = 0; i < NSPLIT; i++) s += g_x2p[(size_t)i * MROWS * F2 + idx];
    g_x2[idx] = gelu_exact(s + b2[idx & (F2 - 1)]);
}

// ---------------- 5) head GEMM: [512,256]@[256,2] + b3 ---------------------
__global__ void head_kernel(const float* __restrict__ W3,
                            const float* __restrict__ b3,
                            float* __restrict__ out) {
    const int row = blockIdx.x;   // 512
    const int tid = threadIdx.x;  // 256
    const float x = g_x2[(size_t)row * F2 + tid];
    __shared__ float sh0[256];
    __shared__ float sh1[256];
    sh0[tid] = x * W3[tid * 2 + 0];
    sh1[tid] = x * W3[tid * 2 + 1];
    __syncthreads();
    for (int o = 128; o > 0; o >>= 1) {
        if (tid < o) { sh0[tid] += sh0[tid + o]; sh1[tid] += sh1[tid + o]; }
        __syncthreads();
    }
    if (tid == 0) {
        out[row * 2 + 0] = sh0[0] + b3[0];
        out[row * 2 + 1] = sh1[0] + b3[1];
    }
}

// ---------------- launch ----------------------------------------------------
extern "C" void kernel_launch(void* const* d_in, const int* in_sizes, int n_in,
                              void* d_out, int out_size) {
    const float* hidden = (const float*)d_in[0];
    const int*   ids32  = (const int*)  d_in[1];   // int32 or int64 (auto-detect)
    const float* W1 = (const float*)d_in[2];
    const float* b1 = (const float*)d_in[3];
    const float* W2 = (const float*)d_in[4];
    const float* b2 = (const float*)d_in[5];
    const float* W3 = (const float*)d_in[6];
    const float* b3 = (const float*)d_in[7];
    float* out = (float*)d_out;

    void *p_sent, *p_x1, *p_x2p;
    cudaGetSymbolAddress(&p_sent, g_sent);
    cudaGetSymbolAddress(&p_x1,   g_x1);
    cudaGetSymbolAddress(&p_x2p,  g_x2p);

    sep_scan_kernel<<<BB, 256>>>(ids32);
    pool_kernel<<<dim3(MS, BB), 256>>>(hidden);

    // GEMM1: [512,768] @ [768,4096] + b1 -> GELU -> g_x1
    sgemm_k<1><<<dim3(F1 / 128, MROWS / 128, 1), 256>>>(
        (const float*)p_sent, W1, b1, (float*)p_x1, MROWS, F1, HH, HH);

    // GEMM2: [512,4096] @ [4096,256], split-K=16 -> partials
    sgemm_k<0><<<dim3(F2 / 128, MROWS / 128, NSPLIT), 256>>>(
        (const float*)p_x1, W2, nullptr, (float*)p_x2p, MROWS, F2, F1, F1 / NSPLIT);

    reduce_gelu_kernel<<<(MROWS * F2) / 256, 256>>>(b2);
    head_kernel<<<MROWS, 256>>>(W3, b3, out);
}